// round 16
// baseline (speedup 1.0000x reference)
#include <cuda_runtime.h>
#include <math_constants.h>

// Problem constants
#define L_OBS   512
#define NSEG    8192
#define BPOSE   8
#define NRAY    (BPOSE * L_OBS)          // 4096
#define FOV_F   6.283185307179586
#define EPS_PAR 0.0001f

// Distance culling radius (map units). Any segment giving a valid hit at
// u <= RCUT has dist(pose, segment) <= RCUT (r is unit), so the culled set is
// exact for all beams that resolve with u <= RCUT. Beams that don't resolve
// within RCUT take the exact full-scan fallback below.
#define RCUT    8.0f
#define R2M     (RCUT * RCUT * 1.0012f)   // conservative margin >> fp32 slop

#define SCH     8                         // segment chunks per pose (merge fan-in)
#define CHSEG   (NSEG / SCH)              // 1024 segs per chunk (2 per thread)
#define TPB     512                       // thread == beam

// Static scratch (zero-initialized at module load; self-resetting each launch)
__device__ unsigned g_best[NRAY];         // ~bits(min u); reset via atomicExch
__device__ int      g_done[BPOSE];        // chunk counter; reset by finalizer

__global__ __launch_bounds__(TPB)
void raycast_kernel(const float4* __restrict__ seg, const float* __restrict__ pose,
                    float* __restrict__ out)
{
    const int pz    = blockIdx.x >> 3;           // pose
    const int chunk = blockIdx.x & (SCH - 1);
    const int tid   = threadIdx.x;               // tid == beam
    const int lane  = tid & 31;

    __shared__ float4 s_pk[CHSEG];   // (sx, sy, dx, dy)
    __shared__ float  s_na[CHSEG];   // num_a
    __shared__ int    s_cnt;
    __shared__ int    s_last;

    if (tid == 0) s_cnt = 0;

    const float px = pose[pz * 3 + 0];
    const float py = pose[pz * 3 + 1];
    const float th = pose[pz * 3 + 2];

    // Beam direction first: MUFU chain overlaps the segment loads below.
    const float kstep = (float)(FOV_F / (double)L_OBS);
    const float ang = (float)tid * kstep + th;
    float rx, ry;
    sincosf(ang, &ry, &rx);
    __syncthreads();

    // ---- phase A: distance cull + compact into smem (2 segments per thread)
    #pragma unroll
    for (int it = 0; it < CHSEG / TPB; ++it) {
        float4 q = seg[chunk * CHSEG + it * TPB + tid];
        float sx = q.z - q.x;
        float sy = q.w - q.y;
        float dx = px - q.x;      // AP = P - A
        float dy = py - q.y;

        // point-to-segment squared distance <= R2M, division-free
        float c    = dx * sx + dy * sy;          // dot(AP, S)
        float s2   = sx * sx + sy * sy;          // |S|^2
        float apsq = dx * dx + dy * dy;
        float bx = dx - sx, by = dy - sy;        // BP = P - B
        float bpsq = bx * bx + by * by;
        bool pass;
        if (c <= 0.0f)      pass = apsq <= R2M;
        else if (c >= s2)   pass = bpsq <= R2M;
        else                pass = (apsq * s2 - c * c) <= R2M * s2;

        unsigned m = __ballot_sync(0xffffffffu, pass);
        if (m) {
            int leader = __ffs(m) - 1;
            int base = 0;
            if (lane == leader) base = atomicAdd(&s_cnt, __popc(m));
            base = __shfl_sync(0xffffffffu, base, leader);
            if (pass) {
                int p = base + __popc(m & ((1u << lane) - 1u));
                s_pk[p] = make_float4(sx, sy, dx, dy);
                s_na[p] = sx * dy - sy * dx;     // num_a (reference formula)
            }
        }
    }
    __syncthreads();

    // ---- phase B: exact test over the compacted list, dual accumulators
    float bn0 = CUDART_INF_F, ba0 = 1.0f;
    float bn1 = CUDART_INF_F, ba1 = 1.0f;
    const int m2 = s_cnt;

    int j = 0;
    #pragma unroll 4
    for (; j + 1 < m2; j += 2) {
        float4 p0  = s_pk[j];
        float  n0  = s_na[j];
        float4 p1  = s_pk[j + 1];
        float  n1  = s_na[j + 1];

        float nb0  = rx * p0.w - ry * p0.z;
        float rxs0 = p0.y * rx - p0.x * ry;
        float aa0  = fabsf(rxs0);
        float an0  = fabsf(n0);
        bool v0 = (aa0 >= EPS_PAR) & (nb0 * rxs0 >= 0.0f)
                & (fabsf(nb0) <= aa0) & (n0 * rxs0 >= 0.0f);
        if (v0 && (an0 * ba0 < bn0 * aa0)) { bn0 = an0; ba0 = aa0; }

        float nb1  = rx * p1.w - ry * p1.z;
        float rxs1 = p1.y * rx - p1.x * ry;
        float aa1  = fabsf(rxs1);
        float an1  = fabsf(n1);
        bool v1 = (aa1 >= EPS_PAR) & (nb1 * rxs1 >= 0.0f)
                & (fabsf(nb1) <= aa1) & (n1 * rxs1 >= 0.0f);
        if (v1 && (an1 * ba1 < bn1 * aa1)) { bn1 = an1; ba1 = aa1; }
    }
    if (j < m2) {
        float4 p0  = s_pk[j];
        float  n0  = s_na[j];
        float nb0  = rx * p0.w - ry * p0.z;
        float rxs0 = p0.y * rx - p0.x * ry;
        float aa0  = fabsf(rxs0);
        float an0  = fabsf(n0);
        bool v0 = (aa0 >= EPS_PAR) & (nb0 * rxs0 >= 0.0f)
                & (fabsf(nb0) <= aa0) & (n0 * rxs0 >= 0.0f);
        if (v0 && (an0 * ba0 < bn0 * aa0)) { bn0 = an0; ba0 = aa0; }
    }
    // merge the two chains
    if (bn1 * ba0 < bn0 * ba1) { bn0 = bn1; ba0 = ba1; }

    const int ray = pz * L_OBS + tid;
    float ublk = bn0 / ba0;                  // inf if nothing valid in chunk
    atomicMax(&g_best[ray], ~__float_as_uint(ublk));

    // ---- last chunk-block of this pose finalizes its 512 beams
    __syncthreads();
    if (tid == 0) {
        __threadfence();
        s_last = (atomicAdd(&g_done[pz], 1) == SCH - 1) ? 1 : 0;
    }
    __syncthreads();
    if (!s_last) return;
    __threadfence();

    unsigned key = atomicExch(&g_best[ray], 0u);   // read + reset for replay
    float u = __uint_as_float(~key);

    // Resolved iff u <= RCUT (any better segment would have dist <= u <= RCUT
    // and thus be in the culled set). Otherwise: exact full scan.
    bool unres = !(u <= RCUT);                     // catches inf and > RCUT
    if (__any_sync(0xffffffffu, unres)) {
        float bn = CUDART_INF_F, ba = 1.0f;
        for (int k = 0; k < NSEG; ++k) {
            float4 q = __ldg(&seg[k]);
            float sx = q.z - q.x;
            float sy = q.w - q.y;
            float dx = px - q.x;
            float dy = py - q.y;
            float nai = sx * dy - sy * dx;
            float nb  = rx * dy - ry * dx;
            float rxs = sy * rx - sx * ry;
            float absa  = fabsf(rxs);
            float absna = fabsf(nai);
            bool valid = (absa >= EPS_PAR) & (nb * rxs >= 0.0f)
                       & (fabsf(nb) <= absa) & (nai * rxs >= 0.0f);
            if (valid && (absna * ba < bn * absa)) { bn = absna; ba = absa; }
        }
        float uf = bn / ba;
        if (isinf(uf)) {
            // Reference: argmin over all-inf returns idx 0 -> u_a[0] (parallel -> 0)
            float4 q = __ldg(&seg[0]);
            float sx = q.z - q.x;
            float sy = q.w - q.y;
            float dx = px - q.x;
            float dy = py - q.y;
            float num_a = sx * dy - sy * dx;
            float rxs   = sy * rx - sx * ry;
            uf = (fabsf(rxs) < EPS_PAR) ? 0.0f : (num_a / rxs);
        }
        if (unres) u = uf;
    }

    const float ix = px + rx * u;
    const float iy = py + ry * u;

    const int gi = ray * 2;
    out[gi + 0] = ix;
    out[gi + 1] = iy;

    float s, c;
    sincosf(th, &s, &c);
    const float ddx = ix - px;
    const float ddy = iy - py;
    out[NRAY * 2 + gi + 0] =  ddx * c + ddy * s;
    out[NRAY * 2 + gi + 1] = -ddx * s + ddy * c;

    if (tid == 0) g_done[pz] = 0;            // reset for next launch/replay
}

extern "C" void kernel_launch(void* const* d_in, const int* in_sizes, int n_in,
                              void* d_out, int out_size)
{
    const float4* seg  = (const float4*)d_in[0];   // line_seg [8192, 4]
    const float*  pose = (const float*)d_in[1];    // pose [8, 3]
    float* out = (float*)d_out;

    raycast_kernel<<<BPOSE * SCH, TPB>>>(seg, pose, out);
}

// round 17
// speedup vs baseline: 1.3276x; 1.3276x over previous
#include <cuda_runtime.h>
#include <math_constants.h>

// Problem constants
#define L_OBS   512
#define NSEG    8192
#define BPOSE   8
#define NRAY    (BPOSE * L_OBS)          // 4096
#define FOV_F   6.283185307179586
#define EPS_PAR 0.0001f

// Distance culling radius (map units). Any segment giving a valid hit at
// u <= RCUT has dist(pose, segment) <= RCUT (r is unit), so the culled set is
// exact for all beams that resolve with u <= RCUT. Beams that don't resolve
// within RCUT take the exact full-scan fallback below.
#define RCUT    8.0f
#define R2M     (RCUT * RCUT * 1.0012f)   // conservative margin >> fp32 slop

#define SCH     16                        // segment chunks per pose
#define CHSEG   (NSEG / SCH)              // 512 segs per chunk (1 per thread)
#define TPB     512                       // thread == beam

// Static scratch. g_part is fully overwritten each launch before it is read
// (done-counter orders writes before the finalize reads) -> no reset needed.
__device__ float g_part[SCH * NRAY];      // per-(chunk, ray) partial min u
__device__ int   g_done[BPOSE];           // chunk counter; reset by finalizer

__global__ __launch_bounds__(TPB)
void raycast_kernel(const float4* __restrict__ seg, const float* __restrict__ pose,
                    float* __restrict__ out)
{
    const int pz    = blockIdx.x >> 4;           // pose
    const int chunk = blockIdx.x & (SCH - 1);
    const int tid   = threadIdx.x;               // tid == beam
    const int lane  = tid & 31;

    __shared__ float4 s_pk[CHSEG];   // (sx, sy, dx, dy)
    __shared__ float  s_na[CHSEG];   // num_a
    __shared__ int    s_cnt;
    __shared__ int    s_last;

    if (tid == 0) s_cnt = 0;

    const float px = pose[pz * 3 + 0];
    const float py = pose[pz * 3 + 1];
    const float th = pose[pz * 3 + 2];

    // Beam direction early: MUFU chain overlaps the segment load below.
    const float kstep = (float)(FOV_F / (double)L_OBS);
    const float ang = (float)tid * kstep + th;
    float rx, ry;
    sincosf(ang, &ry, &rx);
    __syncthreads();

    // ---- phase A: distance cull + compact into smem (1 segment per thread)
    {
        float4 q = seg[chunk * CHSEG + tid];
        float sx = q.z - q.x;
        float sy = q.w - q.y;
        float dx = px - q.x;      // AP = P - A
        float dy = py - q.y;

        // point-to-segment squared distance <= R2M, division-free
        float c    = dx * sx + dy * sy;          // dot(AP, S)
        float s2   = sx * sx + sy * sy;          // |S|^2
        float apsq = dx * dx + dy * dy;
        float bx = dx - sx, by = dy - sy;        // BP = P - B
        float bpsq = bx * bx + by * by;
        bool pass;
        if (c <= 0.0f)      pass = apsq <= R2M;
        else if (c >= s2)   pass = bpsq <= R2M;
        else                pass = (apsq * s2 - c * c) <= R2M * s2;

        unsigned m = __ballot_sync(0xffffffffu, pass);
        if (m) {
            int leader = __ffs(m) - 1;
            int base = 0;
            if (lane == leader) base = atomicAdd(&s_cnt, __popc(m));
            base = __shfl_sync(0xffffffffu, base, leader);
            if (pass) {
                int p = base + __popc(m & ((1u << lane) - 1u));
                s_pk[p] = make_float4(sx, sy, dx, dy);
                s_na[p] = sx * dy - sy * dx;     // num_a (reference formula)
            }
        }
    }
    __syncthreads();

    // ---- phase B: exact test over the compacted list, dual accumulators
    float bn0 = CUDART_INF_F, ba0 = 1.0f;
    float bn1 = CUDART_INF_F, ba1 = 1.0f;
    const int m2 = s_cnt;

    int j = 0;
    #pragma unroll 4
    for (; j + 1 < m2; j += 2) {
        float4 p0  = s_pk[j];
        float  n0  = s_na[j];
        float4 p1  = s_pk[j + 1];
        float  n1  = s_na[j + 1];

        float nb0  = rx * p0.w - ry * p0.z;
        float rxs0 = p0.y * rx - p0.x * ry;
        float aa0  = fabsf(rxs0);
        float an0  = fabsf(n0);
        bool v0 = (aa0 >= EPS_PAR) & (nb0 * rxs0 >= 0.0f)
                & (fabsf(nb0) <= aa0) & (n0 * rxs0 >= 0.0f);
        if (v0 && (an0 * ba0 < bn0 * aa0)) { bn0 = an0; ba0 = aa0; }

        float nb1  = rx * p1.w - ry * p1.z;
        float rxs1 = p1.y * rx - p1.x * ry;
        float aa1  = fabsf(rxs1);
        float an1  = fabsf(n1);
        bool v1 = (aa1 >= EPS_PAR) & (nb1 * rxs1 >= 0.0f)
                & (fabsf(nb1) <= aa1) & (n1 * rxs1 >= 0.0f);
        if (v1 && (an1 * ba1 < bn1 * aa1)) { bn1 = an1; ba1 = aa1; }
    }
    if (j < m2) {
        float4 p0  = s_pk[j];
        float  n0  = s_na[j];
        float nb0  = rx * p0.w - ry * p0.z;
        float rxs0 = p0.y * rx - p0.x * ry;
        float aa0  = fabsf(rxs0);
        float an0  = fabsf(n0);
        bool v0 = (aa0 >= EPS_PAR) & (nb0 * rxs0 >= 0.0f)
                & (fabsf(nb0) <= aa0) & (n0 * rxs0 >= 0.0f);
        if (v0 && (an0 * ba0 < bn0 * aa0)) { bn0 = an0; ba0 = aa0; }
    }
    // merge the two chains
    if (bn1 * ba0 < bn0 * ba1) { bn0 = bn1; ba0 = ba1; }

    const int ray = pz * L_OBS + tid;
    float ublk = bn0 / ba0;                  // inf if nothing valid in chunk
    g_part[chunk * NRAY + ray] = ublk;       // plain STG (no atomic round-trip)

    // ---- last chunk-block of this pose finalizes its 512 beams
    __syncthreads();
    if (tid == 0) {
        __threadfence();
        s_last = (atomicAdd(&g_done[pz], 1) == SCH - 1) ? 1 : 0;
    }
    __syncthreads();
    if (!s_last) return;
    __threadfence();

    // min-reduce the 16 chunk partials (independent loads, MLP=16)
    float u = CUDART_INF_F;
    #pragma unroll
    for (int c = 0; c < SCH; ++c)
        u = fminf(u, g_part[c * NRAY + ray]);

    // Resolved iff u <= RCUT (any better segment would have dist <= u <= RCUT
    // and thus be in the culled set). Otherwise: exact full scan.
    bool unres = !(u <= RCUT);                     // catches inf and > RCUT
    if (__any_sync(0xffffffffu, unres)) {
        float bn = CUDART_INF_F, ba = 1.0f;
        for (int k = 0; k < NSEG; ++k) {
            float4 q = __ldg(&seg[k]);
            float sx = q.z - q.x;
            float sy = q.w - q.y;
            float dx = px - q.x;
            float dy = py - q.y;
            float nai = sx * dy - sy * dx;
            float nb  = rx * dy - ry * dx;
            float rxs = sy * rx - sx * ry;
            float absa  = fabsf(rxs);
            float absna = fabsf(nai);
            bool valid = (absa >= EPS_PAR) & (nb * rxs >= 0.0f)
                       & (fabsf(nb) <= absa) & (nai * rxs >= 0.0f);
            if (valid && (absna * ba < bn * absa)) { bn = absna; ba = absa; }
        }
        float uf = bn / ba;
        if (isinf(uf)) {
            // Reference: argmin over all-inf returns idx 0 -> u_a[0] (parallel -> 0)
            float4 q = __ldg(&seg[0]);
            float sx = q.z - q.x;
            float sy = q.w - q.y;
            float dx = px - q.x;
            float dy = py - q.y;
            float num_a = sx * dy - sy * dx;
            float rxs   = sy * rx - sx * ry;
            uf = (fabsf(rxs) < EPS_PAR) ? 0.0f : (num_a / rxs);
        }
        if (unres) u = uf;
    }

    const float ix = px + rx * u;
    const float iy = py + ry * u;

    const int gi = ray * 2;
    out[gi + 0] = ix;
    out[gi + 1] = iy;

    float s, c;
    sincosf(th, &s, &c);
    const float ddx = ix - px;
    const float ddy = iy - py;
    out[NRAY * 2 + gi + 0] =  ddx * c + ddy * s;
    out[NRAY * 2 + gi + 1] = -ddx * s + ddy * c;

    if (tid == 0) g_done[pz] = 0;            // reset for next launch/replay
}

extern "C" void kernel_launch(void* const* d_in, const int* in_sizes, int n_in,
                              void* d_out, int out_size)
{
    const float4* seg  = (const float4*)d_in[0];   // line_seg [8192, 4]
    const float*  pose = (const float*)d_in[1];    // pose [8, 3]
    float* out = (float*)d_out;

    raycast_kernel<<<BPOSE * SCH, TPB>>>(seg, pose, out);
}